// round 16
// baseline (speedup 1.0000x reference)
#include <cuda_runtime.h>

typedef unsigned long long ull;
typedef unsigned int uint;

#define BB   64
#define CC   768
#define HW   24
#define NPIX 576
#define HID  768
#define KSPL 24
#define KC   32          // KSPL*KC = 768
#define NB   288         // 2 blocks/SM on 148 SMs -> co-resident (<=296)
#define NWG  (NB * 8)    // 2304 pool warp-groups
#define NIT8 (BB * 96)   // 6144 pool items
#define CHUNK 171        // combine elements per block (288*171 >= 49152)

// ---------------- device scratch ----------------
__device__ __align__(16) ull   g_featp[BB * CC];
__device__ __align__(16) ull   g_actp[BB * HID];
__device__ __align__(16) float g_p1[KSPL][BB * HID];
__device__ __align__(16) float g_p2[KSPL][BB * HID];
__device__ int           g_count = 0;
__device__ volatile int  g_sense = 0;

// ---------------- packed fp32 helpers ----------------
__device__ __forceinline__ ull ffma2(ull a, ull b, ull c) {
    ull d;
    asm("fma.rn.f32x2 %0, %1, %2, %3;" : "=l"(d) : "l"(a), "l"(b), "l"(c));
    return d;
}
__device__ __forceinline__ ull fadd2(ull a, ull b) {
    ull d;
    asm("add.rn.f32x2 %0, %1, %2;" : "=l"(d) : "l"(a), "l"(b));
    return d;
}
__device__ __forceinline__ ull dup2(float x) {
    ull d;
    asm("mov.b64 %0, {%1, %1};" : "=l"(d) : "f"(x));
    return d;
}
__device__ __forceinline__ ull pack2(float lo, float hi) {
    ull d;
    asm("mov.b64 %0, {%1, %2};" : "=l"(d) : "f"(lo), "f"(hi));
    return d;
}
__device__ __forceinline__ float lo2(ull p) { return __uint_as_float((uint)p); }
__device__ __forceinline__ float hi2(ull p) { return __uint_as_float((uint)(p >> 32)); }

__device__ __forceinline__ float hat_cdf(float t) {
    if (t <= -1.f) return 0.f;
    if (t <= 0.f) { float u = t + 1.f; return 0.5f * u * u; }
    if (t <= 1.f) { float u = 1.f - t; return 1.f - 0.5f * u * u; }
    return 1.f;
}

// ---------------- grid barrier (proven) ----------------
__device__ __forceinline__ void grid_sync(int ls) {
    __syncthreads();
    __threadfence();
    if (threadIdx.x == 0) {
        if (atomicAdd(&g_count, 1) == NB - 1) {
            g_count = 0;
            __threadfence();
            g_sense = ls;
        } else {
            while (g_sense != ls) { }
        }
    }
    __syncthreads();
    __threadfence();
}

// ---------------- shared memory ----------------
__shared__ float s_wx[BB * 32];              // 8KB   pool
__shared__ float s_wy[BB * 16];              // 4KB   pool
__shared__ int   s_hlo[BB];
__shared__ int   s_hlen[BB];
__shared__ __align__(16) float s_W[KC * 64]; // 8KB   gemm W tile
__shared__ float s_red[8];

// ---------------- GEMM phase: 64r x 64c x KC=32 ----------------
// bid -> x = bid%12 (64-col tile), z = bid/12 (k-chunk). 8 warps x 8 rows.
// lane = 2 cols. W in smem; A lane-uniform broadcast LDG (L2).
__device__ __forceinline__ void gemm_phase(const ull* __restrict__ A,
                                           const float* __restrict__ W,
                                           float* __restrict__ P) {
    const int t = threadIdx.x;
    const int x = blockIdx.x % 12;
    const int z = blockIdx.x / 12;
    const int c0 = x * 64;
    const int k0 = z * KC;

    // stage W [KC x 64]: 512 float4, 2 per thread, coalesced
    #pragma unroll
    for (int j = 0; j < 2; j++) {
        const int e = t + j * 256;
        const int row = e >> 4, col4 = (e & 15) << 2;
        *(float4*)&s_W[row * 64 + col4] =
            *(const float4*)(W + (size_t)(k0 + row) * HID + c0 + col4);
    }
    __syncthreads();

    const int wid = t >> 5, lane = t & 31;
    const ull* ar = A + (size_t)(wid * 8) * HID + k0;   // lane-uniform
    const ull* wu = (const ull*)s_W + lane;

    ull acc[8];
    #pragma unroll
    for (int r = 0; r < 8; r++) acc[r] = 0ull;

    #pragma unroll 4
    for (int k = 0; k < KC; k += 2) {
        const ull w0 = wu[k * 32];
        const ull w1 = wu[k * 32 + 32];
        #pragma unroll
        for (int r = 0; r < 8; r++) {
            ulonglong2 a2 = *(const ulonglong2*)(ar + (size_t)r * HID + k);
            acc[r] = ffma2(a2.x, w0, acc[r]);
            acc[r] = ffma2(a2.y, w1, acc[r]);
        }
    }

    float* op = P + (size_t)z * (BB * HID)
              + (size_t)(wid * 8) * HID + c0 + lane * 2;
    #pragma unroll
    for (int r = 0; r < 8; r++)
        *(ull*)(op + (size_t)r * HID) = acc[r];
    __syncthreads();   // s_W reused next phase
}

// ================= THE single fused kernel =================
__global__ __launch_bounds__(256, 2) void fused_kernel(
    const float* __restrict__ X,  const float* __restrict__ sb,
    const float* __restrict__ w1, const float* __restrict__ b1,
    const float* __restrict__ w2, const float* __restrict__ b2,
    const float* __restrict__ w3, const float* __restrict__ b3,
    float* __restrict__ out)
{
    const int bid = blockIdx.x;
    const int t = threadIdx.x;
    const int wid = t >> 5, lane = t & 31;

    // ---- phase 0a: per-batch wx/wy tables (redundant per block) ----
    for (int e = t; e < BB * 32; e += 256) {
        const int b = e >> 5, w = e & 31;
        float x0 = sb[b * 4 + 0] * (float)HW;
        float x1 = sb[b * 4 + 2] * (float)HW;
        float v = 0.f;
        if (w < HW) v = hat_cdf(x1 - (float)w) - hat_cdf(x0 - (float)w);
        s_wx[e] = v;
    }
    for (int e = t; e < BB * 16; e += 256) {
        const int b = e >> 4, i = e & 15;
        float x0 = sb[b * 4 + 0] * (float)HW;
        float y0 = sb[b * 4 + 1] * (float)HW;
        float x1 = sb[b * 4 + 2] * (float)HW;
        float y1 = sb[b * 4 + 3] * (float)HW;
        float scale = 1.f / ((x1 - x0) * (y1 - y0));
        int hlo = max(0, (int)floorf(y0 - 1.f) + 1);
        int hhi = min(HW - 1, (int)ceilf(y1 + 1.f) - 1);
        if (i == 0) { s_hlo[b] = hlo; s_hlen[b] = hhi - hlo + 1; }
        int h = hlo + i;
        float v = 0.f;
        if (h <= hhi)
            v = (hat_cdf(y1 - (float)h) - hat_cdf(y0 - (float)h)) * scale;
        s_wy[e] = v;
    }
    __syncthreads();

    // ---- phase 0b: pool (R8 per-warp code; <=3 items per warp) ----
    {
        const int wg = bid * 8 + wid;
        for (int it = wg; it < NIT8; it += NWG) {
            const int b = it / 96;
            const int c0 = b * CC + (it - b * 96) * 8;
            const int hl = s_hlo[b], n = s_hlen[b];
            const float* base = X + (size_t)c0 * NPIX + hl * HW + lane;
            const float* wyp = s_wy + b * 16;

            float a0 = 0.f, a1 = 0.f, a2 = 0.f, a3 = 0.f;
            float a4 = 0.f, a5 = 0.f, a6 = 0.f, a7 = 0.f;
            if (lane < HW) {
                int off = 0;
                #pragma unroll 2
                for (int i = 0; i < n; i++, off += HW) {
                    const float wy = wyp[i];
                    const float* p = base + off;
                    a0 = fmaf(wy, __ldg(p + 0 * NPIX), a0);
                    a1 = fmaf(wy, __ldg(p + 1 * NPIX), a1);
                    a2 = fmaf(wy, __ldg(p + 2 * NPIX), a2);
                    a3 = fmaf(wy, __ldg(p + 3 * NPIX), a3);
                    a4 = fmaf(wy, __ldg(p + 4 * NPIX), a4);
                    a5 = fmaf(wy, __ldg(p + 5 * NPIX), a5);
                    a6 = fmaf(wy, __ldg(p + 6 * NPIX), a6);
                    a7 = fmaf(wy, __ldg(p + 7 * NPIX), a7);
                }
                const float wx = s_wx[b * 32 + lane];
                a0 *= wx; a1 *= wx; a2 *= wx; a3 *= wx;
                a4 *= wx; a5 *= wx; a6 *= wx; a7 *= wx;
            }
            ull p0 = pack2(a0, a1), p1 = pack2(a2, a3);
            ull p2 = pack2(a4, a5), p3 = pack2(a6, a7);
            #pragma unroll
            for (int sh = 16; sh; sh >>= 1) {
                p0 = fadd2(p0, __shfl_xor_sync(0xffffffffu, p0, sh));
                p1 = fadd2(p1, __shfl_xor_sync(0xffffffffu, p1, sh));
                p2 = fadd2(p2, __shfl_xor_sync(0xffffffffu, p2, sh));
                p3 = fadd2(p3, __shfl_xor_sync(0xffffffffu, p3, sh));
            }
            if (lane == 0) {
                g_featp[c0 + 0] = dup2(lo2(p0));
                g_featp[c0 + 1] = dup2(hi2(p0));
                g_featp[c0 + 2] = dup2(lo2(p1));
                g_featp[c0 + 3] = dup2(hi2(p1));
                g_featp[c0 + 4] = dup2(lo2(p2));
                g_featp[c0 + 5] = dup2(hi2(p2));
                g_featp[c0 + 6] = dup2(lo2(p3));
                g_featp[c0 + 7] = dup2(hi2(p3));
            }
        }
    }

    grid_sync(1);

    // ---- phase 1: GEMM 1 ----
    gemm_phase(g_featp, w1, &g_p1[0][0]);

    grid_sync(0);

    // ---- phase 2: combine + bias + relu + pack ----
    {
        const int s0 = bid * CHUNK;
        const int e0 = min(s0 + CHUNK, BB * HID);
        for (int idx = s0 + t; idx < e0; idx += 256) {
            const int c = idx % HID;
            float v = b1[c];
            #pragma unroll
            for (int z = 0; z < KSPL; z++) v += g_p1[z][idx];
            g_actp[idx] = dup2(fmaxf(v, 0.f));
        }
    }

    grid_sync(1);

    // ---- phase 3: GEMM 2 ----
    gemm_phase(g_actp, w2, &g_p2[0][0]);

    grid_sync(0);

    // ---- phase 4: final combine + dot(w3) ----
    if (bid < BB) {
        float acc = 0.f;
        #pragma unroll
        for (int j = 0; j < 3; j++) {
            const int k = t + j * 256;
            const int idx = bid * HID + k;
            float v = b2[k];
            #pragma unroll
            for (int z = 0; z < KSPL; z++) v += g_p2[z][idx];
            acc = fmaf(fmaxf(v, 0.f), w3[k], acc);
        }
        #pragma unroll
        for (int sh = 16; sh; sh >>= 1) acc += __shfl_xor_sync(0xffffffffu, acc, sh);
        if (lane == 0) s_red[wid] = acc;
        __syncthreads();
        if (t == 0) {
            float r = s_red[0] + s_red[1] + s_red[2] + s_red[3] +
                      s_red[4] + s_red[5] + s_red[6] + s_red[7];
            out[bid] = r + b3[0];
        }
    }
}

// ---------------- launch ----------------
extern "C" void kernel_launch(void* const* d_in, const int* in_sizes, int n_in,
                              void* d_out, int out_size) {
    const float* X  = (const float*)d_in[0];
    const float* sb = (const float*)d_in[1];
    const float* w1 = (const float*)d_in[2];
    const float* b1 = (const float*)d_in[3];
    const float* w2 = (const float*)d_in[4];
    const float* b2 = (const float*)d_in[5];
    const float* w3 = (const float*)d_in[6];
    const float* b3 = (const float*)d_in[7];
    float* out = (float*)d_out;

    fused_kernel<<<NB, 256>>>(X, sb, w1, b1, w2, b2, w3, b3, out);
}

// round 17
// speedup vs baseline: 2.0338x; 2.0338x over previous
#include <cuda_runtime.h>

typedef unsigned long long ull;
typedef unsigned int uint;

#define BB   64
#define CC   768
#define HW   24
#define NPIX 576
#define HID  768
#define KSPL 24
#define KC   32         // KSPL*KC = 768
#define NIT8 (BB * 96)  // pool items

// ---------------- device scratch ----------------
__device__ __align__(16) ull   g_featp[BB * CC];
__device__ __align__(16) ull   g_actp[BB * HID];
__device__ __align__(16) float g_p1[KSPL][BB * HID];
__device__ __align__(16) float g_p2[KSPL][BB * HID];

// ---------------- packed fp32 helpers ----------------
__device__ __forceinline__ ull ffma2(ull a, ull b, ull c) {
    ull d;
    asm("fma.rn.f32x2 %0, %1, %2, %3;" : "=l"(d) : "l"(a), "l"(b), "l"(c));
    return d;
}
__device__ __forceinline__ ull fadd2(ull a, ull b) {
    ull d;
    asm("add.rn.f32x2 %0, %1, %2;" : "=l"(d) : "l"(a), "l"(b));
    return d;
}
__device__ __forceinline__ ull dup2(float x) {
    ull d;
    asm("mov.b64 %0, {%1, %1};" : "=l"(d) : "f"(x));
    return d;
}
__device__ __forceinline__ ull pack2(float lo, float hi) {
    ull d;
    asm("mov.b64 %0, {%1, %2};" : "=l"(d) : "f"(lo), "f"(hi));
    return d;
}
__device__ __forceinline__ float lo2(ull p) { return __uint_as_float((uint)p); }
__device__ __forceinline__ float hi2(ull p) { return __uint_as_float((uint)(p >> 32)); }

// Coherent loads for data written by the PDL predecessor (read-once, so free).
__device__ __forceinline__ ulonglong2 ld_cg_u64x2(const ull* p) {
    ulonglong2 v;
    asm volatile("ld.global.cg.v2.u64 {%0, %1}, [%2];"
                 : "=l"(v.x), "=l"(v.y) : "l"(p));
    return v;
}
__device__ __forceinline__ float ld_cg_f32(const float* p) {
    float v;
    asm volatile("ld.global.cg.f32 %0, [%1];" : "=f"(v) : "l"(p));
    return v;
}

// PDL: trigger at kernel START (all CTAs) so the dependent grid prelaunches
// and overlaps its prologue with this kernel's execution. wait() blocks until
// the predecessor GRID COMPLETES (full memory visibility), so any read of
// predecessor-written data after wait() is ordered; .cg avoids stale L1.
__device__ __forceinline__ void pdl_trigger_early() {
    asm volatile("griddepcontrol.launch_dependents;" ::: "memory");
}
__device__ __forceinline__ void pdl_wait() {
    asm volatile("griddepcontrol.wait;" ::: "memory");
}

__device__ __forceinline__ float hat_cdf(float t) {
    if (t <= -1.f) return 0.f;
    if (t <= 0.f) { float u = t + 1.f; return 0.5f * u * u; }
    if (t <= 1.f) { float u = 1.f - t; return 1.f - 0.5f * u * u; }
    return 1.f;
}

// ================= kernel 1: pool (R8 verbatim + early trigger) =============
__global__ __launch_bounds__(256) void pool_kernel(
    const float* __restrict__ X, const float* __restrict__ sb)
{
    __shared__ float s_wx[BB * 32];
    __shared__ float s_wy[BB * 16];
    __shared__ int   s_hlo[BB];
    __shared__ int   s_hlen[BB];

    pdl_trigger_early();   // gemm1 prelaunches; its W1 staging overlaps us

    const int t = threadIdx.x;
    const int wid = t >> 5, lane = t & 31;

    for (int e = t; e < BB * 32; e += 256) {
        const int b = e >> 5, w = e & 31;
        float x0 = sb[b * 4 + 0] * (float)HW;
        float x1 = sb[b * 4 + 2] * (float)HW;
        float v = 0.f;
        if (w < HW) v = hat_cdf(x1 - (float)w) - hat_cdf(x0 - (float)w);
        s_wx[e] = v;
    }
    for (int e = t; e < BB * 16; e += 256) {
        const int b = e >> 4, i = e & 15;
        float x0 = sb[b * 4 + 0] * (float)HW;
        float y0 = sb[b * 4 + 1] * (float)HW;
        float x1 = sb[b * 4 + 2] * (float)HW;
        float y1 = sb[b * 4 + 3] * (float)HW;
        float scale = 1.f / ((x1 - x0) * (y1 - y0));
        int hlo = max(0, (int)floorf(y0 - 1.f) + 1);
        int hhi = min(HW - 1, (int)ceilf(y1 + 1.f) - 1);
        if (i == 0) { s_hlo[b] = hlo; s_hlen[b] = hhi - hlo + 1; }
        int h = hlo + i;
        float v = 0.f;
        if (h <= hhi)
            v = (hat_cdf(y1 - (float)h) - hat_cdf(y0 - (float)h)) * scale;
        s_wy[e] = v;
    }
    __syncthreads();

    const int it = blockIdx.x * 8 + wid;
    if (it >= NIT8) return;
    const int b = it / 96;
    const int c0 = b * CC + (it - b * 96) * 8;
    const int hl = s_hlo[b], n = s_hlen[b];
    const float* base = X + (size_t)c0 * NPIX + hl * HW + lane;
    const float* wyp = s_wy + b * 16;

    float a0 = 0.f, a1 = 0.f, a2 = 0.f, a3 = 0.f;
    float a4 = 0.f, a5 = 0.f, a6 = 0.f, a7 = 0.f;
    if (lane < HW) {
        int off = 0;
        #pragma unroll 2
        for (int i = 0; i < n; i++, off += HW) {
            const float wy = wyp[i];
            const float* p = base + off;
            a0 = fmaf(wy, __ldg(p + 0 * NPIX), a0);
            a1 = fmaf(wy, __ldg(p + 1 * NPIX), a1);
            a2 = fmaf(wy, __ldg(p + 2 * NPIX), a2);
            a3 = fmaf(wy, __ldg(p + 3 * NPIX), a3);
            a4 = fmaf(wy, __ldg(p + 4 * NPIX), a4);
            a5 = fmaf(wy, __ldg(p + 5 * NPIX), a5);
            a6 = fmaf(wy, __ldg(p + 6 * NPIX), a6);
            a7 = fmaf(wy, __ldg(p + 7 * NPIX), a7);
        }
        const float wx = s_wx[b * 32 + lane];
        a0 *= wx; a1 *= wx; a2 *= wx; a3 *= wx;
        a4 *= wx; a5 *= wx; a6 *= wx; a7 *= wx;
    }
    ull p0 = pack2(a0, a1), p1 = pack2(a2, a3);
    ull p2 = pack2(a4, a5), p3 = pack2(a6, a7);
    #pragma unroll
    for (int sh = 16; sh; sh >>= 1) {
        p0 = fadd2(p0, __shfl_xor_sync(0xffffffffu, p0, sh));
        p1 = fadd2(p1, __shfl_xor_sync(0xffffffffu, p1, sh));
        p2 = fadd2(p2, __shfl_xor_sync(0xffffffffu, p2, sh));
        p3 = fadd2(p3, __shfl_xor_sync(0xffffffffu, p3, sh));
    }
    if (lane == 0) {
        g_featp[c0 + 0] = dup2(lo2(p0));
        g_featp[c0 + 1] = dup2(hi2(p0));
        g_featp[c0 + 2] = dup2(lo2(p1));
        g_featp[c0 + 3] = dup2(hi2(p1));
        g_featp[c0 + 4] = dup2(lo2(p2));
        g_featp[c0 + 5] = dup2(hi2(p2));
        g_featp[c0 + 6] = dup2(lo2(p3));
        g_featp[c0 + 7] = dup2(hi2(p3));
    }
}

// ================= kernel 2/4: GEMM, smem W + smem A (R11 mainloop) ========
// grid (12, 24): x = 64-col tile, y = k-chunk KC=32. 256 thr = 8 warps.
// Prologue (pre-wait): stage W (immutable). Post-wait: stage A with .cg.
__global__ __launch_bounds__(256, 2) void gemm_kernel(
    const ull* A, const float* __restrict__ W, float* __restrict__ P)
{
    __shared__ __align__(16) ull   s_A[64 * KC];   // 16KB packed (a,a)
    __shared__ __align__(16) float s_W[KC * 64];   // 8KB

    pdl_trigger_early();   // next kernel prelaunches its prologue

    const int t = threadIdx.x;
    const int c0 = blockIdx.x * 64;
    const int k0 = blockIdx.y * KC;

    // prologue: stage W tile [KC x 64] coalesced (overlaps predecessor)
    #pragma unroll
    for (int j = 0; j < 2; j++) {
        const int e = t + j * 256;
        const int row = e >> 4, col4 = (e & 15) << 2;
        *(float4*)&s_W[row * 64 + col4] =
            *(const float4*)(W + (size_t)(k0 + row) * HID + c0 + col4);
    }

    pdl_wait();   // predecessor grid complete; A is final

    // stage A tile [64 rows x KC] with coherent loads: 64B per thread
    {
        const int row = t >> 2, seg = (t & 3) * 8;
        const ull* src = A + (size_t)row * HID + k0 + seg;
        ull* dst = s_A + row * KC + seg;
        #pragma unroll
        for (int j = 0; j < 8; j += 2) {
            ulonglong2 v = ld_cg_u64x2(src + j);
            *(ulonglong2*)(dst + j) = v;
        }
    }
    __syncthreads();

    const int wid = t >> 5, lane = t & 31;
    const ull* ar = s_A + (wid * 8) * KC;
    const ull* wu = (const ull*)s_W + lane;

    ull acc[8];
    #pragma unroll
    for (int r = 0; r < 8; r++) acc[r] = 0ull;

    #pragma unroll 4
    for (int k = 0; k < KC; k += 2) {
        const ull w0 = wu[k * 32];
        const ull w1 = wu[k * 32 + 32];
        #pragma unroll
        for (int r = 0; r < 8; r++) {
            ulonglong2 a2 = *(const ulonglong2*)(ar + r * KC + k);
            acc[r] = ffma2(a2.x, w0, acc[r]);
            acc[r] = ffma2(a2.y, w1, acc[r]);
        }
    }

    float* op = P + (size_t)blockIdx.y * (BB * HID)
              + (size_t)(wid * 8) * HID + c0 + lane * 2;
    #pragma unroll
    for (int r = 0; r < 8; r++)
        *(ull*)(op + (size_t)r * HID) = acc[r];
}

// ================= kernel 3: combine + bias + relu + pack =================
__global__ __launch_bounds__(512) void combine_kernel(const float* __restrict__ bias) {
    pdl_trigger_early();
    const int idx = blockIdx.x * 512 + threadIdx.x;   // 96*512 = 49152
    const int c = idx % HID;
    float v = bias[c];        // immutable input: pre-wait prologue
    pdl_wait();
    #pragma unroll
    for (int z = 0; z < KSPL; z++) v += ld_cg_f32(&g_p1[z][idx]);
    g_actp[idx] = dup2(fmaxf(v, 0.f));
}

// ================= kernel 5: final combine + dot(w3) =================
__global__ __launch_bounds__(256) void final_kernel(
    const float* __restrict__ b2, const float* __restrict__ w3,
    const float* __restrict__ b3, float* __restrict__ out)
{
    __shared__ float red[8];
    const int b = blockIdx.x, t = threadIdx.x;
    const int wid = t >> 5, lane = t & 31;

    // prologue: immutable inputs
    float bias[3], wv[3];
    #pragma unroll
    for (int j = 0; j < 3; j++) {
        bias[j] = b2[t + j * 256];
        wv[j]   = w3[t + j * 256];
    }
    const float b3v = b3[0];

    pdl_wait();

    float acc = 0.f;
    #pragma unroll
    for (int j = 0; j < 3; j++) {
        const int idx = b * HID + t + j * 256;
        float v = bias[j];
        #pragma unroll
        for (int z = 0; z < KSPL; z++) v += ld_cg_f32(&g_p2[z][idx]);
        acc = fmaf(fmaxf(v, 0.f), wv[j], acc);
    }
    #pragma unroll
    for (int sh = 16; sh; sh >>= 1) acc += __shfl_xor_sync(0xffffffffu, acc, sh);
    if (lane == 0) red[wid] = acc;
    __syncthreads();
    if (t == 0) {
        float r = red[0] + red[1] + red[2] + red[3] +
                  red[4] + red[5] + red[6] + red[7];
        out[b] = r + b3v;
    }
}

// ---------------- launch (PDL on every edge) ----------------
template <typename K, typename... Args>
static void launch_pdl(dim3 grid, dim3 block, K kern, Args... args) {
    cudaLaunchConfig_t cfg = {};
    cfg.gridDim = grid;
    cfg.blockDim = block;
    cfg.dynamicSmemBytes = 0;
    cfg.stream = 0;
    cudaLaunchAttribute at[1];
    at[0].id = cudaLaunchAttributeProgrammaticStreamSerialization;
    at[0].val.programmaticStreamSerializationAllowed = 1;
    cfg.attrs = at;
    cfg.numAttrs = 1;
    cudaLaunchKernelEx(&cfg, kern, args...);
}

extern "C" void kernel_launch(void* const* d_in, const int* in_sizes, int n_in,
                              void* d_out, int out_size) {
    const float* X  = (const float*)d_in[0];
    const float* sb = (const float*)d_in[1];
    const float* w1 = (const float*)d_in[2];
    const float* b1 = (const float*)d_in[3];
    const float* w2 = (const float*)d_in[4];
    const float* b2 = (const float*)d_in[5];
    const float* w3 = (const float*)d_in[6];
    const float* b3 = (const float*)d_in[7];
    float* out = (float*)d_out;

    ull* featp; cudaGetSymbolAddress((void**)&featp, g_featp);
    ull* actp;  cudaGetSymbolAddress((void**)&actp,  g_actp);
    float* p1;  cudaGetSymbolAddress((void**)&p1, g_p1);
    float* p2;  cudaGetSymbolAddress((void**)&p2, g_p2);

    launch_pdl(dim3(768), dim3(256), pool_kernel, X, sb);
    launch_pdl(dim3(12, 24), dim3(256), gemm_kernel, (const ull*)featp, w1, p1);
    launch_pdl(dim3(96), dim3(512), combine_kernel, b1);
    launch_pdl(dim3(12, 24), dim3(256), gemm_kernel, (const ull*)actp, w2, p2);
    launch_pdl(dim3(64), dim3(256), final_kernel, b2, w3, b3, out);
}